// round 5
// baseline (speedup 1.0000x reference)
#include <cuda_runtime.h>
#include <cstdint>

// ---------------------------------------------------------------------------
// Problem constants (shapes fixed by setup_inputs)
// ---------------------------------------------------------------------------
#define N_NODES 50000
#define N_EDGES 400000
#define F_IN    256
#define HID     64
#define N_CLS   32
#define HEADS   8

// ---------------------------------------------------------------------------
// Static scratch (no cudaMalloc allowed)
// ---------------------------------------------------------------------------
__device__ float g_xl1[N_NODES * HEADS * HID];   // 102.4 MB
__device__ float g_xr1[N_NODES * HEADS * HID];   // 102.4 MB
__device__ float g_h1 [N_NODES * HID];           // 12.8 MB
__device__ float g_xl2[N_NODES * HEADS * N_CLS]; // 51.2 MB
__device__ float g_xr2[N_NODES * HEADS * N_CLS]; // 51.2 MB
__device__ int   g_deg   [N_NODES];
__device__ int   g_rowptr[N_NODES + 1];
__device__ int   g_cursor[N_NODES];
__device__ int   g_csr   [N_EDGES + N_NODES];    // edges + self loops
__device__ int   g_is64;                         // edge_index dtype flag

// ---------------------------------------------------------------------------
// edge_index dtype probe (int64 => all high words zero since ids < 2^31).
// ---------------------------------------------------------------------------
__global__ void k_flag_init() { g_is64 = 1; }

__global__ void k_detect(const int* __restrict__ p, int nPairs) {
    int i = blockIdx.x * blockDim.x + threadIdx.x;
    if (i < nPairs && p[2 * i + 1] != 0) g_is64 = 0;   // benign race: only writes 0
}

__device__ __forceinline__ int edge_at(const int* __restrict__ p, int e) {
    if (g_is64) return (int)(((const long long*)p)[e]);
    return p[e];
}

// ---------------------------------------------------------------------------
// CSR build kernels (dst-major, self loops included, range-guarded)
// ---------------------------------------------------------------------------
__global__ void k_init_deg(int* __restrict__ deg, int n) {
    int i = blockIdx.x * blockDim.x + threadIdx.x;
    if (i < n) deg[i] = 1;   // self loop counts as one incoming edge
}

__global__ void k_hist(const int* __restrict__ ei, int E, int* __restrict__ deg) {
    int e = blockIdx.x * blockDim.x + threadIdx.x;
    if (e < E) {
        unsigned d = (unsigned)edge_at(ei, E + e);
        unsigned s = (unsigned)edge_at(ei, e);
        if (d < (unsigned)N_NODES && s < (unsigned)N_NODES)
            atomicAdd(&deg[d], 1);
    }
}

// Single-block exclusive scan (Hillis-Steele over 1024-wide chunks).
__global__ void k_scan(const int* __restrict__ deg, int* __restrict__ rowptr, int n) {
    __shared__ int sm[1024];
    __shared__ int s_carry;
    int t = threadIdx.x;
    if (t == 0) s_carry = 0;
    __syncthreads();
    for (int base = 0; base < n; base += 1024) {
        int i = base + t;
        int v = (i < n) ? deg[i] : 0;
        sm[t] = v;
        __syncthreads();
        #pragma unroll
        for (int off = 1; off < 1024; off <<= 1) {
            int add = (t >= off) ? sm[t - off] : 0;
            __syncthreads();
            sm[t] += add;
            __syncthreads();
        }
        int incl = sm[t];
        int carry = s_carry;
        if (i < n) rowptr[i] = carry + incl - v;   // exclusive
        __syncthreads();
        if (t == 1023) s_carry = carry + incl;
        __syncthreads();
    }
    if (t == 0) rowptr[n] = s_carry;
}

// Fused: cursor init + self-loop scatter (self loop goes first in each segment)
__global__ void k_cursor_self(const int* __restrict__ rowptr, int* __restrict__ cur,
                              int* __restrict__ csr, int n) {
    int i = blockIdx.x * blockDim.x + threadIdx.x;
    if (i < n) {
        int p = rowptr[i];
        csr[p] = i;
        cur[i] = p + 1;
    }
}

__global__ void k_scatter_edges(const int* __restrict__ ei, int E,
                                int* __restrict__ cur, int* __restrict__ csr) {
    int e = blockIdx.x * blockDim.x + threadIdx.x;
    if (e < E) {
        unsigned s = (unsigned)edge_at(ei, e);
        unsigned d = (unsigned)edge_at(ei, E + e);
        if (d < (unsigned)N_NODES && s < (unsigned)N_NODES)
            csr[atomicAdd(&cur[d], 1)] = (int)s;
    }
}

// ---------------------------------------------------------------------------
// fp32 SGEMM v2: C[M,N] = A[M,K] @ B[K,N] (+ bias[n]).
// 128x128x16 block tile, 256 threads, 8x8 microtile, register double-buffered
// global->smem pipeline (LDG of tile t+1 overlaps FMA on tile t; single
// __syncthreads per k-tile). Requires K % 16 == 0 (K in {256,64}).
// ---------------------------------------------------------------------------
__global__ void __launch_bounds__(256)
k_sgemm(const float* __restrict__ A, const float* __restrict__ B,
        float* __restrict__ C, int M, int N, int K,
        const float* __restrict__ bias) {
    constexpr int BM = 128, BN = 128, BK = 16;
    __shared__ float As[2][BK][BM];   // transposed: As[k][m]
    __shared__ float Bs[2][BK][BN];

    const int tid = threadIdx.x;
    const int bm = blockIdx.y * BM;
    const int bn = blockIdx.x * BN;
    const int tx = tid & 15;       // 0..15 -> N (8 cols each)
    const int ty = tid >> 4;       // 0..15 -> M (8 rows each)

    // A tile loads: 128 rows x 16 k = 512 float4s / 256 thr = 2 per thread
    const int aRow = tid >> 1;              // 0..127
    const int aK   = (tid & 1) * 4;         // 0 or 4 (second load at +8)
    // B tile loads: 16 rows x 128 cols = 512 float4s / 256 thr = 2 per thread
    const int bRow = tid >> 5;              // 0..7 (second load at +8)
    const int bCol = (tid & 31) * 4;        // 0..124

    const bool aOk = (bm + aRow) < M;
    const bool bOk = (bn + bCol) < N;
    const float4 z4 = make_float4(0.f, 0.f, 0.f, 0.f);
    const float* aBase = A + (size_t)(bm + aRow) * K;

    float4 aReg0, aReg1, bReg0, bReg1;

    // prologue: load tile 0
    aReg0 = aOk ? *(const float4*)(aBase + aK)     : z4;
    aReg1 = aOk ? *(const float4*)(aBase + aK + 8) : z4;
    bReg0 = bOk ? *(const float4*)(B + (size_t)(bRow)     * N + bn + bCol) : z4;
    bReg1 = bOk ? *(const float4*)(B + (size_t)(bRow + 8) * N + bn + bCol) : z4;

    float acc[8][8];
    #pragma unroll
    for (int i = 0; i < 8; ++i)
        #pragma unroll
        for (int j = 0; j < 8; ++j) acc[i][j] = 0.f;

    const int nt = K / BK;

    // store tile 0
    {
        const float* a0 = &aReg0.x; const float* a1 = &aReg1.x;
        #pragma unroll
        for (int j = 0; j < 4; ++j) {
            As[0][aK + j][aRow]     = a0[j];
            As[0][aK + 8 + j][aRow] = a1[j];
        }
        *(float4*)&Bs[0][bRow][bCol]     = bReg0;
        *(float4*)&Bs[0][bRow + 8][bCol] = bReg1;
    }
    __syncthreads();

    for (int t = 0; t < nt; ++t) {
        const int cur = t & 1;
        if (t + 1 < nt) {
            const int k0 = (t + 1) * BK;
            aReg0 = aOk ? *(const float4*)(aBase + k0 + aK)     : z4;
            aReg1 = aOk ? *(const float4*)(aBase + k0 + aK + 8) : z4;
            bReg0 = bOk ? *(const float4*)(B + (size_t)(k0 + bRow)     * N + bn + bCol) : z4;
            bReg1 = bOk ? *(const float4*)(B + (size_t)(k0 + bRow + 8) * N + bn + bCol) : z4;
        }

        #pragma unroll
        for (int kk = 0; kk < BK; ++kk) {
            float4 a0 = *(const float4*)&As[cur][kk][ty * 8];
            float4 a1 = *(const float4*)&As[cur][kk][ty * 8 + 4];
            float4 b0 = *(const float4*)&Bs[cur][kk][tx * 8];
            float4 b1 = *(const float4*)&Bs[cur][kk][tx * 8 + 4];
            float a[8] = {a0.x, a0.y, a0.z, a0.w, a1.x, a1.y, a1.z, a1.w};
            float b[8] = {b0.x, b0.y, b0.z, b0.w, b1.x, b1.y, b1.z, b1.w};
            #pragma unroll
            for (int i = 0; i < 8; ++i)
                #pragma unroll
                for (int j = 0; j < 8; ++j)
                    acc[i][j] = fmaf(a[i], b[j], acc[i][j]);
        }

        if (t + 1 < nt) {
            const int nxt = cur ^ 1;
            const float* a0 = &aReg0.x; const float* a1 = &aReg1.x;
            #pragma unroll
            for (int j = 0; j < 4; ++j) {
                As[nxt][aK + j][aRow]     = a0[j];
                As[nxt][aK + 8 + j][aRow] = a1[j];
            }
            *(float4*)&Bs[nxt][bRow][bCol]     = bReg0;
            *(float4*)&Bs[nxt][bRow + 8][bCol] = bReg1;
            __syncthreads();
        }
    }

    #pragma unroll
    for (int i = 0; i < 8; ++i) {
        int row = bm + ty * 8 + i;
        if (row >= M) continue;
        #pragma unroll
        for (int j = 0; j < 8; ++j) {
            int col = bn + tx * 8 + j;
            if (col < N) {
                float v = acc[i][j];
                if (bias) v += bias[col];
                C[(size_t)row * N + col] = v;
            }
        }
    }
}

// ---------------------------------------------------------------------------
// GATv2 edge+softmax+aggregate, fused per dst node.
// One block per dst node, 8 warps = 8 heads, lane = channel (C/32 chans/lane).
// alpha = exp(logit)/denom done as unnormalized sum then divide (no max-shift;
// logits are O(1) so fp32 exp is safe; ratio is mathematically identical).
// ---------------------------------------------------------------------------
template <int C, bool RELU, bool ADD_RES>
__global__ void __launch_bounds__(256)
k_gatv2(const float* __restrict__ xl, const float* __restrict__ xr,
        const float* __restrict__ att, const float* __restrict__ bias,
        const int* __restrict__ rowptr, const int* __restrict__ csr,
        const float* __restrict__ resid, float* __restrict__ out) {
    constexpr int H = HEADS;
    constexpr int KC = C / 32;       // channels per lane (2 for C=64, 1 for C=32)
    int node = blockIdx.x;
    int w = threadIdx.x >> 5;        // head
    int l = threadIdx.x & 31;        // lane

    const float* xr_row = xr + (size_t)node * H * C + w * C;
    float xrv[KC], attv[KC], accv[KC];
    #pragma unroll
    for (int k = 0; k < KC; ++k) {
        xrv[k]  = xr_row[l + 32 * k];
        attv[k] = att[w * C + l + 32 * k];
        accv[k] = 0.f;
    }
    float denom = 0.f;

    int beg = rowptr[node], end = rowptr[node + 1];
    for (int idx = beg; idx < end; ++idx) {
        int s = csr[idx];
        const float* xl_row = xl + (size_t)s * H * C + w * C;
        float xlv[KC];
        float partial = 0.f;
        #pragma unroll
        for (int k = 0; k < KC; ++k) {
            xlv[k] = xl_row[l + 32 * k];
            float v = xlv[k] + xrv[k];
            v = (v > 0.f) ? v : 0.2f * v;      // leaky_relu(0.2)
            partial = fmaf(attv[k], v, partial);
        }
        #pragma unroll
        for (int off = 16; off > 0; off >>= 1)
            partial += __shfl_xor_sync(0xffffffffu, partial, off);
        float p = __expf(partial);
        denom += p;
        #pragma unroll
        for (int k = 0; k < KC; ++k)
            accv[k] = fmaf(p, xlv[k], accv[k]);
    }

    // head mean via smem
    __shared__ float sh[H * C];
    float inv = 1.f / denom;
    #pragma unroll
    for (int k = 0; k < KC; ++k)
        sh[w * C + l + 32 * k] = accv[k] * inv;
    __syncthreads();

    if (threadIdx.x < C) {
        int c = threadIdx.x;
        float s = 0.f;
        #pragma unroll
        for (int h = 0; h < H; ++h) s += sh[h * C + c];
        s = s * (1.f / H) + bias[c];
        if (RELU) s = fmaxf(s, 0.f);
        if (ADD_RES) s += resid[(size_t)node * C + c];
        out[(size_t)node * C + c] = s;
    }
}

// ---------------------------------------------------------------------------
// Launch. Order chosen so ncu's `-s 5 -c 1` capture lands on a big layer-1
// GEMM instead of a microscopic CSR kernel.
// ---------------------------------------------------------------------------
static inline int cdiv(int a, int b) { return (a + b - 1) / b; }

extern "C" void kernel_launch(void* const* d_in, const int* in_sizes, int n_in,
                              void* d_out, int out_size) {
    const float* x    = (const float*)d_in[0];
    const int*   ei   = (const int*)d_in[1];     // int32 or int64, detected on device
    const float* Wl1  = (const float*)d_in[2];
    const float* Wr1  = (const float*)d_in[3];
    const float* att1 = (const float*)d_in[4];
    const float* b1   = (const float*)d_in[5];
    const float* Wl2  = (const float*)d_in[6];
    const float* Wr2  = (const float*)d_in[7];
    const float* att2 = (const float*)d_in[8];
    const float* b2   = (const float*)d_in[9];
    const float* Wlin = (const float*)d_in[10];
    const float* blin = (const float*)d_in[11];
    float* out = (float*)d_out;

    const int N = in_sizes[0] / F_IN;   // 50000
    const int E = in_sizes[1] / 2;      // 400000 (element count, dtype-independent)

    float *xl1, *xr1, *xl2, *xr2, *h1;
    int *deg, *rowptr, *cursor, *csr;
    cudaGetSymbolAddress((void**)&xl1,    g_xl1);
    cudaGetSymbolAddress((void**)&xr1,    g_xr1);
    cudaGetSymbolAddress((void**)&h1,     g_h1);
    cudaGetSymbolAddress((void**)&xl2,    g_xl2);
    cudaGetSymbolAddress((void**)&xr2,    g_xr2);
    cudaGetSymbolAddress((void**)&deg,    g_deg);
    cudaGetSymbolAddress((void**)&rowptr, g_rowptr);
    cudaGetSymbolAddress((void**)&cursor, g_cursor);
    cudaGetSymbolAddress((void**)&csr,    g_csr);

    // ---- dtype detect + degree histogram (launches 1-4) ----
    k_flag_init<<<1, 1>>>();
    k_detect<<<cdiv(E, 256), 256>>>(ei, E);
    k_init_deg<<<cdiv(N, 256), 256>>>(deg, N);
    k_hist<<<cdiv(E, 256), 256>>>(ei, E, deg);

    // ---- Layer-1 transforms + residual (launches 5-7; ncu captures here) ----
    {
        dim3 g(cdiv(HEADS * HID, 128), cdiv(N, 128));      // N=512
        k_sgemm<<<g, 256>>>(x, Wl1, xl1, N, HEADS * HID, F_IN, nullptr);
        k_sgemm<<<g, 256>>>(x, Wr1, xr1, N, HEADS * HID, F_IN, nullptr);
    }
    {
        dim3 g(cdiv(N_CLS, 128), cdiv(N, 128));            // N=32 -> residual into d_out
        k_sgemm<<<g, 256>>>(x, Wlin, out, N, N_CLS, F_IN, blin);
    }

    // ---- finish CSR build ----
    k_scan<<<1, 1024>>>(deg, rowptr, N);
    k_cursor_self<<<cdiv(N, 256), 256>>>(rowptr, cursor, csr, N);
    k_scatter_edges<<<cdiv(E, 256), 256>>>(ei, E, cursor, csr);

    // ---- GAT layer 1 (relu) -> h1 ----
    k_gatv2<HID, true, false><<<N, 256>>>(xl1, xr1, att1, b1, rowptr, csr, nullptr, h1);

    // ---- Layer-2 transforms ----
    {
        dim3 g(cdiv(HEADS * N_CLS, 128), cdiv(N, 128));    // N=256
        k_sgemm<<<g, 256>>>(h1, Wl2, xl2, N, HEADS * N_CLS, HID, nullptr);
        k_sgemm<<<g, 256>>>(h1, Wr2, xr2, N, HEADS * N_CLS, HID, nullptr);
    }

    // ---- GAT layer 2 + residual -> d_out ----
    k_gatv2<N_CLS, false, true><<<N, 256>>>(xl2, xr2, att2, b2, rowptr, csr, out, out);
}

// round 7
// speedup vs baseline: 1.5305x; 1.5305x over previous
#include <cuda_runtime.h>
#include <cstdint>

// ---------------------------------------------------------------------------
// Problem constants
// ---------------------------------------------------------------------------
#define N_NODES 50000
#define N_EDGES 400000
#define F_IN    256
#define HID     64
#define N_CLS   32
#define HEADS   8

// ---------------------------------------------------------------------------
// Static scratch (no cudaMalloc allowed)
// ---------------------------------------------------------------------------
__device__ float g_xl1[N_NODES * HEADS * HID];   // 102.4 MB
__device__ float g_xr1[N_NODES * HEADS * HID];   // 102.4 MB
__device__ float g_h1 [N_NODES * HID];           // 12.8 MB
__device__ float g_xl2[N_NODES * HEADS * N_CLS]; // 51.2 MB
__device__ float g_xr2[N_NODES * HEADS * N_CLS]; // 51.2 MB
__device__ int   g_deg   [N_NODES];
__device__ int   g_rowptr[N_NODES + 1];
__device__ int   g_cursor[N_NODES];
__device__ int   g_csr   [N_EDGES + N_NODES];
__device__ int   g_is64;

// ---------------------------------------------------------------------------
// edge_index dtype probe (int64 => all high words zero since ids < 2^31).
// ---------------------------------------------------------------------------
__global__ void k_flag_init() { g_is64 = 1; }

__global__ void k_detect(const int* __restrict__ p, int nPairs) {
    int i = blockIdx.x * blockDim.x + threadIdx.x;
    if (i < nPairs && p[2 * i + 1] != 0) g_is64 = 0;   // benign race: only writes 0
}

__device__ __forceinline__ int edge_at(const int* __restrict__ p, int e) {
    if (g_is64) return (int)(((const long long*)p)[e]);
    return p[e];
}

// ---------------------------------------------------------------------------
// CSR build kernels (dst-major, self loops included, range-guarded)
// ---------------------------------------------------------------------------
__global__ void k_init_deg(int* __restrict__ deg, int n) {
    int i = blockIdx.x * blockDim.x + threadIdx.x;
    if (i < n) deg[i] = 1;
}

__global__ void k_hist(const int* __restrict__ ei, int E, int* __restrict__ deg) {
    int e = blockIdx.x * blockDim.x + threadIdx.x;
    if (e < E) {
        unsigned d = (unsigned)edge_at(ei, E + e);
        unsigned s = (unsigned)edge_at(ei, e);
        if (d < (unsigned)N_NODES && s < (unsigned)N_NODES)
            atomicAdd(&deg[d], 1);
    }
}

__global__ void k_scan(const int* __restrict__ deg, int* __restrict__ rowptr, int n) {
    __shared__ int sm[1024];
    __shared__ int s_carry;
    int t = threadIdx.x;
    if (t == 0) s_carry = 0;
    __syncthreads();
    for (int base = 0; base < n; base += 1024) {
        int i = base + t;
        int v = (i < n) ? deg[i] : 0;
        sm[t] = v;
        __syncthreads();
        #pragma unroll
        for (int off = 1; off < 1024; off <<= 1) {
            int add = (t >= off) ? sm[t - off] : 0;
            __syncthreads();
            sm[t] += add;
            __syncthreads();
        }
        int incl = sm[t];
        int carry = s_carry;
        if (i < n) rowptr[i] = carry + incl - v;
        __syncthreads();
        if (t == 1023) s_carry = carry + incl;
        __syncthreads();
    }
    if (t == 0) rowptr[n] = s_carry;
}

__global__ void k_cursor_self(const int* __restrict__ rowptr, int* __restrict__ cur,
                              int* __restrict__ csr, int n) {
    int i = blockIdx.x * blockDim.x + threadIdx.x;
    if (i < n) {
        int p = rowptr[i];
        csr[p] = i;
        cur[i] = p + 1;
    }
}

__global__ void k_scatter_edges(const int* __restrict__ ei, int E,
                                int* __restrict__ cur, int* __restrict__ csr) {
    int e = blockIdx.x * blockDim.x + threadIdx.x;
    if (e < E) {
        unsigned s = (unsigned)edge_at(ei, e);
        unsigned d = (unsigned)edge_at(ei, E + e);
        if (d < (unsigned)N_NODES && s < (unsigned)N_NODES)
            csr[atomicAdd(&cur[d], 1)] = (int)s;
    }
}

// ---------------------------------------------------------------------------
// tf32 tensor-core GEMM with fp32-accurate 3-term compensation.
// C[M,N] = A[M,K] @ B[K,N] (+bias). Block 128x64x8, 8 warps (4Mx2N),
// warp tile 32x32 (2 m-frags x 4 n-frags of m16n8k8). cp.async double buffer.
// A*B = Ahi*Bhi + Alo*Bhi + Ahi*Blo  (lo = tf32(a - float(tf32(a)))).
// Requires K % 8 == 0, N % 4 == 0.
// ---------------------------------------------------------------------------
__device__ __forceinline__ unsigned f2tf32(float x) {
    unsigned r;
    asm("cvt.rna.tf32.f32 %0, %1;" : "=r"(r) : "f"(x));
    return r;
}

__device__ __forceinline__ void mma_tf32(float* c, const unsigned* a, const unsigned* b) {
    asm volatile(
        "mma.sync.aligned.m16n8k8.row.col.f32.tf32.tf32.f32 "
        "{%0,%1,%2,%3}, {%4,%5,%6,%7}, {%8,%9}, {%0,%1,%2,%3};"
        : "+f"(c[0]), "+f"(c[1]), "+f"(c[2]), "+f"(c[3])
        : "r"(a[0]), "r"(a[1]), "r"(a[2]), "r"(a[3]), "r"(b[0]), "r"(b[1]));
}

__device__ __forceinline__ void cp16(void* dst_smem, const void* src, bool pred) {
    unsigned saddr = (unsigned)__cvta_generic_to_shared(dst_smem);
    int sz = pred ? 16 : 0;
    asm volatile("cp.async.cg.shared.global [%0], [%1], 16, %2;"
                 :: "r"(saddr), "l"(src), "r"(sz));
}

__global__ void __launch_bounds__(256)
k_mma(const float* __restrict__ A, const float* __restrict__ B,
      float* __restrict__ C, int M, int N, int K,
      const float* __restrict__ bias) {
    constexpr int BM = 128, BN = 64, BK = 8;
    __shared__ alignas(16) float As[2][BM][12];   // [m][k], stride 12 (pad, 16B-aligned rows)
    __shared__ alignas(16) float Bs[2][BK][68];   // [k][n], stride 68

    const int tid  = threadIdx.x;
    const int lane = tid & 31;
    const int wid  = tid >> 5;
    const int warpM = wid >> 1;       // 0..3  -> m offset *32
    const int warpN = wid & 1;        // 0..1  -> n offset *32
    const int gid = lane >> 2;        // 0..7
    const int tig = lane & 3;         // 0..3

    const int bm = blockIdx.y * BM;
    const int bn = blockIdx.x * BN;

    // global->smem load assignments
    const int aRow  = tid >> 1;             // 0..127
    const int aHalf = (tid & 1) * 4;        // 0 or 4
    const bool aOk  = (bm + aRow) < M;
    const int bRow  = (tid & 127) >> 4;     // 0..7 (only tid<128 loads B)
    const int bCol  = (tid & 15) * 4;       // 0..60
    const bool bOk  = (bn + bCol) < N;

    float acc[2][4][4];                      // [mfrag][nfrag][4]
    #pragma unroll
    for (int i = 0; i < 2; ++i)
        #pragma unroll
        for (int j = 0; j < 4; ++j)
            #pragma unroll
            for (int r = 0; r < 4; ++r) acc[i][j][r] = 0.f;

    const int nt = K / BK;

    // prologue: tile 0
    cp16(&As[0][aRow][aHalf],
         aOk ? (const void*)(A + (size_t)(bm + aRow) * K + aHalf) : (const void*)A, aOk);
    if (tid < 128)
        cp16(&Bs[0][bRow][bCol],
             bOk ? (const void*)(B + (size_t)bRow * N + bn + bCol) : (const void*)B, bOk);
    asm volatile("cp.async.commit_group;");
    asm volatile("cp.async.wait_group 0;" ::: "memory");
    __syncthreads();

    for (int t = 0; t < nt; ++t) {
        const int cur = t & 1;
        if (t + 1 < nt) {
            const int k0 = (t + 1) * BK;
            const int nxt = cur ^ 1;
            cp16(&As[nxt][aRow][aHalf],
                 aOk ? (const void*)(A + (size_t)(bm + aRow) * K + k0 + aHalf) : (const void*)A, aOk);
            if (tid < 128)
                cp16(&Bs[nxt][bRow][bCol],
                     bOk ? (const void*)(B + (size_t)(k0 + bRow) * N + bn + bCol) : (const void*)B, bOk);
            asm volatile("cp.async.commit_group;");
        }

        // ---- load fragments + split hi/lo ----
        unsigned ahi[2][4], alo[2][4], bhi[4][2], blo[4][2];
        #pragma unroll
        for (int mf = 0; mf < 2; ++mf) {
            const int mb = warpM * 32 + mf * 16;
            float e0 = As[cur][mb + gid    ][tig];
            float e1 = As[cur][mb + gid + 8][tig];
            float e2 = As[cur][mb + gid    ][tig + 4];
            float e3 = As[cur][mb + gid + 8][tig + 4];
            float e[4] = {e0, e1, e2, e3};
            #pragma unroll
            for (int r = 0; r < 4; ++r) {
                unsigned h = f2tf32(e[r]);
                ahi[mf][r] = h;
                alo[mf][r] = f2tf32(e[r] - __uint_as_float(h));
            }
        }
        #pragma unroll
        for (int nf = 0; nf < 4; ++nf) {
            const int nb = warpN * 32 + nf * 8;
            float e0 = Bs[cur][tig    ][nb + gid];
            float e1 = Bs[cur][tig + 4][nb + gid];
            unsigned h0 = f2tf32(e0), h1 = f2tf32(e1);
            bhi[nf][0] = h0; bhi[nf][1] = h1;
            blo[nf][0] = f2tf32(e0 - __uint_as_float(h0));
            blo[nf][1] = f2tf32(e1 - __uint_as_float(h1));
        }

        // ---- 2x4 frag pairs, 3 compensated MMAs each ----
        #pragma unroll
        for (int mf = 0; mf < 2; ++mf)
            #pragma unroll
            for (int nf = 0; nf < 4; ++nf) {
                mma_tf32(acc[mf][nf], alo[mf], bhi[nf]);
                mma_tf32(acc[mf][nf], ahi[mf], blo[nf]);
                mma_tf32(acc[mf][nf], ahi[mf], bhi[nf]);
            }

        if (t + 1 < nt) {
            asm volatile("cp.async.wait_group 0;" ::: "memory");
            __syncthreads();
        }
    }

    // ---- epilogue ----
    #pragma unroll
    for (int mf = 0; mf < 2; ++mf) {
        #pragma unroll
        for (int nf = 0; nf < 4; ++nf) {
            const int col0 = bn + warpN * 32 + nf * 8 + 2 * tig;
            const int row0 = bm + warpM * 32 + mf * 16 + gid;
            #pragma unroll
            for (int half = 0; half < 2; ++half) {
                const int row = row0 + half * 8;
                if (row >= M) continue;
                #pragma unroll
                for (int c = 0; c < 2; ++c) {
                    const int col = col0 + c;
                    if (col < N) {
                        float v = acc[mf][nf][half * 2 + c];
                        if (bias) v += bias[col];
                        C[(size_t)row * N + col] = v;
                    }
                }
            }
        }
    }
}

// ---------------------------------------------------------------------------
// GATv2 edge+softmax+aggregate, fused per dst node (unchanged, known-good).
// ---------------------------------------------------------------------------
template <int C, bool RELU, bool ADD_RES>
__global__ void __launch_bounds__(256)
k_gatv2(const float* __restrict__ xl, const float* __restrict__ xr,
        const float* __restrict__ att, const float* __restrict__ bias,
        const int* __restrict__ rowptr, const int* __restrict__ csr,
        const float* __restrict__ resid, float* __restrict__ out) {
    constexpr int H = HEADS;
    constexpr int KC = C / 32;
    int node = blockIdx.x;
    int w = threadIdx.x >> 5;
    int l = threadIdx.x & 31;

    const float* xr_row = xr + (size_t)node * H * C + w * C;
    float xrv[KC], attv[KC], accv[KC];
    #pragma unroll
    for (int k = 0; k < KC; ++k) {
        xrv[k]  = xr_row[l + 32 * k];
        attv[k] = att[w * C + l + 32 * k];
        accv[k] = 0.f;
    }
    float denom = 0.f;

    int beg = rowptr[node], end = rowptr[node + 1];
    for (int idx = beg; idx < end; ++idx) {
        int s = csr[idx];
        const float* xl_row = xl + (size_t)s * H * C + w * C;
        float xlv[KC];
        float partial = 0.f;
        #pragma unroll
        for (int k = 0; k < KC; ++k) {
            xlv[k] = xl_row[l + 32 * k];
            float v = xlv[k] + xrv[k];
            v = (v > 0.f) ? v : 0.2f * v;
            partial = fmaf(attv[k], v, partial);
        }
        #pragma unroll
        for (int off = 16; off > 0; off >>= 1)
            partial += __shfl_xor_sync(0xffffffffu, partial, off);
        float p = __expf(partial);
        denom += p;
        #pragma unroll
        for (int k = 0; k < KC; ++k)
            accv[k] = fmaf(p, xlv[k], accv[k]);
    }

    __shared__ float sh[H * C];
    float inv = 1.f / denom;
    #pragma unroll
    for (int k = 0; k < KC; ++k)
        sh[w * C + l + 32 * k] = accv[k] * inv;
    __syncthreads();

    if (threadIdx.x < C) {
        int c = threadIdx.x;
        float s = 0.f;
        #pragma unroll
        for (int h = 0; h < H; ++h) s += sh[h * C + c];
        s = s * (1.f / H) + bias[c];
        if (RELU) s = fmaxf(s, 0.f);
        if (ADD_RES) s += resid[(size_t)node * C + c];
        out[(size_t)node * C + c] = s;
    }
}

// ---------------------------------------------------------------------------
// Launch
// ---------------------------------------------------------------------------
static inline int cdiv(int a, int b) { return (a + b - 1) / b; }

extern "C" void kernel_launch(void* const* d_in, const int* in_sizes, int n_in,
                              void* d_out, int out_size) {
    const float* x    = (const float*)d_in[0];
    const int*   ei   = (const int*)d_in[1];
    const float* Wl1  = (const float*)d_in[2];
    const float* Wr1  = (const float*)d_in[3];
    const float* att1 = (const float*)d_in[4];
    const float* b1   = (const float*)d_in[5];
    const float* Wl2  = (const float*)d_in[6];
    const float* Wr2  = (const float*)d_in[7];
    const float* att2 = (const float*)d_in[8];
    const float* b2   = (const float*)d_in[9];
    const float* Wlin = (const float*)d_in[10];
    const float* blin = (const float*)d_in[11];
    float* out = (float*)d_out;

    const int N = in_sizes[0] / F_IN;   // 50000
    const int E = in_sizes[1] / 2;      // 400000

    float *xl1, *xr1, *xl2, *xr2, *h1;
    int *deg, *rowptr, *cursor, *csr;
    cudaGetSymbolAddress((void**)&xl1,    g_xl1);
    cudaGetSymbolAddress((void**)&xr1,    g_xr1);
    cudaGetSymbolAddress((void**)&h1,     g_h1);
    cudaGetSymbolAddress((void**)&xl2,    g_xl2);
    cudaGetSymbolAddress((void**)&xr2,    g_xr2);
    cudaGetSymbolAddress((void**)&deg,    g_deg);
    cudaGetSymbolAddress((void**)&rowptr, g_rowptr);
    cudaGetSymbolAddress((void**)&cursor, g_cursor);
    cudaGetSymbolAddress((void**)&csr,    g_csr);

    // ---- dtype detect + degree histogram ----
    k_flag_init<<<1, 1>>>();
    k_detect<<<cdiv(E, 256), 256>>>(ei, E);
    k_init_deg<<<cdiv(N, 256), 256>>>(deg, N);
    k_hist<<<cdiv(E, 256), 256>>>(ei, E, deg);

    // ---- Layer-1 transforms + residual (tensor-core GEMMs) ----
    {
        dim3 g(cdiv(HEADS * HID, 64), cdiv(N, 128));       // 8 x 391
        k_mma<<<g, 256>>>(x, Wl1, xl1, N, HEADS * HID, F_IN, nullptr);
        k_mma<<<g, 256>>>(x, Wr1, xr1, N, HEADS * HID, F_IN, nullptr);
    }
    {
        dim3 g(cdiv(N_CLS, 64), cdiv(N, 128));             // 1 x 391 -> residual
        k_mma<<<g, 256>>>(x, Wlin, out, N, N_CLS, F_IN, blin);
    }

    // ---- finish CSR build ----
    k_scan<<<1, 1024>>>(deg, rowptr, N);
    k_cursor_self<<<cdiv(N, 256), 256>>>(rowptr, cursor, csr, N);
    k_scatter_edges<<<cdiv(E, 256), 256>>>(ei, E, cursor, csr);

    // ---- GAT layer 1 (relu) -> h1 ----
    k_gatv2<HID, true, false><<<N, 256>>>(xl1, xr1, att1, b1, rowptr, csr, nullptr, h1);

    // ---- Layer-2 transforms ----
    {
        dim3 g(cdiv(HEADS * N_CLS, 64), cdiv(N, 128));     // 4 x 391
        k_mma<<<g, 256>>>(h1, Wl2, xl2, N, HEADS * N_CLS, HID, nullptr);
        k_mma<<<g, 256>>>(h1, Wr2, xr2, N, HEADS * N_CLS, HID, nullptr);
    }

    // ---- GAT layer 2 + residual -> d_out ----
    k_gatv2<N_CLS, false, true><<<N, 256>>>(xl2, xr2, att2, b2, rowptr, csr, out, out);
}